// round 15
// baseline (speedup 1.0000x reference)
#include <cuda_runtime.h>
#include <cstdint>

#define N_NODES 300000
#define DIM 128
#define KNBR 5
#define EPS_LN 1e-5f
#define BLOCK 64
#define NTHREADS 256
#define NTILES ((N_NODES + BLOCK - 1) / BLOCK)
#define PAD 72      // stride (floats) of k-major tiles
#define TQS 132     // stride of row-major Q buffer
#define WS 132      // stride (floats) of weight smem rows

// k-major node rotation: element (row r, node n) lives at r*PAD + ((n + KROT(r)) & 63)
#define KROT(r) ((((r) >> 4) & 3) << 3)
// W column rotation: row r, col c lives at r*WS + ((c + WROT(r)) & 127)
#define WROT(r) (((r) & 2) << 2)

typedef unsigned long long ull;

// ---------------- global scratch ----------------
__device__ float g_Kp1[(size_t)N_NODES * DIM];
__device__ float g_Vp1[(size_t)N_NODES * DIM];
__device__ float g_Kp2[(size_t)N_NODES * DIM];
__device__ float g_Vp2[(size_t)N_NODES * DIM];
__device__ float g_H[(size_t)N_NODES * 256];   // FFN hidden scratch
__device__ float g_rowsum[N_NODES];

// ---------------- helpers ----------------
__device__ __forceinline__ unsigned sptr(const void* p) {
    return (unsigned)__cvta_generic_to_shared(p);
}
__device__ __forceinline__ void cp16(unsigned saddr, const void* g) {
    asm volatile("cp.async.cg.shared.global [%0], [%1], 16;" :: "r"(saddr), "l"(g));
}
__device__ __forceinline__ void cp_commit() {
    asm volatile("cp.async.commit_group;" ::: "memory");
}
__device__ __forceinline__ void cp_waitall() {
    asm volatile("cp.async.wait_group 0;" ::: "memory");
}
__device__ __forceinline__ void cp_wait() {
    asm volatile("cp.async.commit_group;\n\tcp.async.wait_group 0;" ::: "memory");
}
__device__ __forceinline__ unsigned cvt_tf32(float x) {
    unsigned r;
    asm("cvt.rna.tf32.f32 %0, %1;" : "=r"(r) : "f"(x));
    return r;
}
// m16n8k8 tf32 mma: D = A@B + D (fp32 accum)
__device__ __forceinline__ void mma8(float c[4], unsigned a0, unsigned a1,
                                     unsigned a2, unsigned a3,
                                     unsigned b0, unsigned b1) {
    asm volatile(
        "mma.sync.aligned.m16n8k8.row.col.f32.tf32.tf32.f32 "
        "{%0,%1,%2,%3},{%4,%5,%6,%7},{%8,%9},{%0,%1,%2,%3};"
        : "+f"(c[0]), "+f"(c[1]), "+f"(c[2]), "+f"(c[3])
        : "r"(a0), "r"(a1), "r"(a2), "r"(a3), "r"(b0), "r"(b1));
}

// ---------------- shared memory layouts ----------------
struct SmemMain {
    float XT[DIM * PAD];   // residual stream, k-major rotated
    float W[64 * WS];      // weight k-chunk, column-rotated
    float S[DIM * PAD];    // scratch: Tq | AT | U | H-half | F
    int   nidx[BLOCK * KNBR];
    int   nmask[BLOCK * KNBR];
};                          // ~107.5 KB -> 2 CTAs/SM
struct SmemPre {
    float XT[DIM * PAD];
    float W[64 * WS];
};                          // ~69 KB -> 3 CTAs/SM

// ---------------- W chunk loaders (cp.async, 64 rows x 128 cols, stride WS) ----
__device__ __forceinline__ void issue_chunk(const float* __restrict__ Wg,
                                            int row0, int col0, int ncols,
                                            float* __restrict__ Ws) {
    int tid = threadIdx.x;
    #pragma unroll
    for (int i = tid; i < 2048; i += NTHREADS) {   // 2048 float4
        int r  = i >> 5;
        int c4 = (i & 31) << 2;
        int pc = (c4 + WROT(r)) & 127;             // column rotation
        cp16(sptr(Ws + r * WS + pc),
             Wg + (size_t)(row0 + r) * ncols + col0 + c4);
    }
}
__device__ __forceinline__ void stage_chunk(const float* __restrict__ Wg,
                                            int row0, int col0, int ncols,
                                            float* __restrict__ Ws) {
    __syncthreads();
    issue_chunk(Wg, row0, col0, ncols, Ws);
    cp_wait();
    __syncthreads();
}

__device__ __forceinline__ void zc(float c[8][4]) {
    #pragma unroll
    for (int j = 0; j < 8; ++j)
        #pragma unroll
        for (int i = 0; i < 4; ++i) c[j][i] = 0.f;
}

// C[64x128] += A(k-major rotated, stride PAD) @ W(smem col-rotated, stride WS)
// Warp tile m16 x n64; mma-j covers logical columns n0 + 8c + j.
__device__ __forceinline__ void gemm64_mma(const float* __restrict__ A,
                                           const float* __restrict__ W,
                                           int m0, int n0, int g, int tg,
                                           float c[8][4]) {
    #pragma unroll
    for (int ks = 0; ks < 8; ++ks) {
        int r    = ks * 8 + tg;
        int rot  = ((ks >> 1) & 3) << 3;           // KROT(r), lane-invariant
        const float* ar = A + r * PAD;
        int p0 = (m0 + g + rot) & 63;
        int p1 = (m0 + g + 8 + rot) & 63;
        unsigned a0 = cvt_tf32(ar[p0]);
        unsigned a1 = cvt_tf32(ar[p1]);
        unsigned a2 = cvt_tf32(ar[4 * PAD + p0]);
        unsigned a3 = cvt_tf32(ar[4 * PAD + p1]);
        int wrot = (tg & 2) << 2;                  // WROT(r), r&2 == tg&2
        const float* wr = W + r * WS;
        int cb0 = (n0 + 8 * g + wrot) & 127;
        int cb1 = (n0 + 8 * g + 4 + wrot) & 127;
        float4 b0a = *(const float4*)(wr + cb0);
        float4 b0b = *(const float4*)(wr + cb1);
        float4 b1a = *(const float4*)(wr + 4 * WS + cb0);
        float4 b1b = *(const float4*)(wr + 4 * WS + cb1);
        float b0v[8] = {b0a.x, b0a.y, b0a.z, b0a.w, b0b.x, b0b.y, b0b.z, b0b.w};
        float b1v[8] = {b1a.x, b1a.y, b1a.z, b1a.w, b1b.x, b1b.y, b1b.z, b1b.w};
        #pragma unroll
        for (int j = 0; j < 8; ++j)
            mma8(c[j], a0, a1, a2, a3,
                 __float_as_uint(b0v[j]), __float_as_uint(b1v[j]));
    }
}

// store C frags to k-major rotated buffer with bias (+optional relu)
__device__ __forceinline__ void store_frag(float* __restrict__ Dst,
                                           const float* __restrict__ bias,
                                           bool relu, int m0, int n0,
                                           int g, int tg, const float c[8][4]) {
    int rot = tg << 3;
    int pm0 = (m0 + g + rot) & 63;
    int pm1 = (m0 + g + 8 + rot) & 63;
    #pragma unroll
    for (int j = 0; j < 8; ++j) {
        int na = n0 + 16 * tg + j;
        int nb = na + 8;
        float ba_ = bias[na], bb_ = bias[nb];
        float v0 = c[j][0] + ba_, v1 = c[j][1] + bb_;
        float v2 = c[j][2] + ba_, v3 = c[j][3] + bb_;
        if (relu) {
            v0 = fmaxf(v0, 0.f); v1 = fmaxf(v1, 0.f);
            v2 = fmaxf(v2, 0.f); v3 = fmaxf(v3, 0.f);
        }
        Dst[(size_t)na * PAD + pm0] = v0;
        Dst[(size_t)nb * PAD + pm0] = v1;
        Dst[(size_t)na * PAD + pm1] = v2;
        Dst[(size_t)nb * PAD + pm1] = v3;
    }
}

// store C frags to g_H (row-major, 256 cols) with bias + relu
__device__ __forceinline__ void store_frag_gH(int base, int colbase,
                                              const float* __restrict__ bias,
                                              int m0, int n0, int g, int tg,
                                              const float c[8][4]) {
    int gm0 = base + m0 + g;
    int gm1 = gm0 + 8;
    int nb0 = n0 + 16 * tg;           // bias index base (within 0..127)
    float4 r0a = make_float4(fmaxf(c[0][0] + bias[nb0+0], 0.f), fmaxf(c[1][0] + bias[nb0+1], 0.f),
                             fmaxf(c[2][0] + bias[nb0+2], 0.f), fmaxf(c[3][0] + bias[nb0+3], 0.f));
    float4 r0b = make_float4(fmaxf(c[4][0] + bias[nb0+4], 0.f), fmaxf(c[5][0] + bias[nb0+5], 0.f),
                             fmaxf(c[6][0] + bias[nb0+6], 0.f), fmaxf(c[7][0] + bias[nb0+7], 0.f));
    float4 r0c = make_float4(fmaxf(c[0][1] + bias[nb0+8], 0.f), fmaxf(c[1][1] + bias[nb0+9], 0.f),
                             fmaxf(c[2][1] + bias[nb0+10], 0.f), fmaxf(c[3][1] + bias[nb0+11], 0.f));
    float4 r0d = make_float4(fmaxf(c[4][1] + bias[nb0+12], 0.f), fmaxf(c[5][1] + bias[nb0+13], 0.f),
                             fmaxf(c[6][1] + bias[nb0+14], 0.f), fmaxf(c[7][1] + bias[nb0+15], 0.f));
    float4 r1a = make_float4(fmaxf(c[0][2] + bias[nb0+0], 0.f), fmaxf(c[1][2] + bias[nb0+1], 0.f),
                             fmaxf(c[2][2] + bias[nb0+2], 0.f), fmaxf(c[3][2] + bias[nb0+3], 0.f));
    float4 r1b = make_float4(fmaxf(c[4][2] + bias[nb0+4], 0.f), fmaxf(c[5][2] + bias[nb0+5], 0.f),
                             fmaxf(c[6][2] + bias[nb0+6], 0.f), fmaxf(c[7][2] + bias[nb0+7], 0.f));
    float4 r1c = make_float4(fmaxf(c[0][3] + bias[nb0+8], 0.f), fmaxf(c[1][3] + bias[nb0+9], 0.f),
                             fmaxf(c[2][3] + bias[nb0+10], 0.f), fmaxf(c[3][3] + bias[nb0+11], 0.f));
    float4 r1d = make_float4(fmaxf(c[4][3] + bias[nb0+12], 0.f), fmaxf(c[5][3] + bias[nb0+13], 0.f),
                             fmaxf(c[6][3] + bias[nb0+14], 0.f), fmaxf(c[7][3] + bias[nb0+15], 0.f));
    if (gm0 < N_NODES) {
        float* p = g_H + (size_t)gm0 * 256 + colbase + nb0;
        *(float4*)(p)      = r0a;
        *(float4*)(p + 4)  = r0b;
        *(float4*)(p + 8)  = r0c;
        *(float4*)(p + 12) = r0d;
    }
    if (gm1 < N_NODES) {
        float* p = g_H + (size_t)gm1 * 256 + colbase + nb0;
        *(float4*)(p)      = r1a;
        *(float4*)(p + 4)  = r1b;
        *(float4*)(p + 8)  = r1c;
        *(float4*)(p + 12) = r1d;
    }
}

// LN: XT = LN(XT + UT)*gamma + beta (both k-major rotated). 2 units per thread.
__device__ __forceinline__ void ln_t(float* __restrict__ XT,
                                     const float* __restrict__ UT,
                                     const float* __restrict__ gamma,
                                     const float* __restrict__ beta) {
    int tid = threadIdx.x;
    #pragma unroll
    for (int u = 0; u < 2; ++u) {
        int idx  = tid + u * NTHREADS;
        int node = idx >> 3;
        int h    = idx & 7;
        float v[16];
        float sum = 0.f;
        #pragma unroll
        for (int i = 0; i < 16; ++i) {
            int e  = h + 8 * i;
            int pn = (node + (((i >> 1) & 3) << 3)) & 63;   // KROT(e)
            v[i] = XT[e * PAD + pn] + UT[e * PAD + pn];
            sum += v[i];
        }
        sum += __shfl_xor_sync(0xffffffffu, sum, 1);
        sum += __shfl_xor_sync(0xffffffffu, sum, 2);
        sum += __shfl_xor_sync(0xffffffffu, sum, 4);
        float m = sum * (1.f / 128.f);
        float sq = 0.f;
        #pragma unroll
        for (int i = 0; i < 16; ++i) { float d = v[i] - m; sq = fmaf(d, d, sq); }
        sq += __shfl_xor_sync(0xffffffffu, sq, 1);
        sq += __shfl_xor_sync(0xffffffffu, sq, 2);
        sq += __shfl_xor_sync(0xffffffffu, sq, 4);
        float inv = rsqrtf(sq * (1.f / 128.f) + EPS_LN);
        #pragma unroll
        for (int i = 0; i < 16; ++i) {
            int e  = h + 8 * i;
            int pn = (node + (((i >> 1) & 3) << 3)) & 63;
            XT[e * PAD + pn] = (v[i] - m) * inv * gamma[e] + beta[e];
        }
    }
}

// ---------------- one transformer layer ----------------
__device__ void run_layer(SmemMain* s, int base,
                          const float* wq, const float* wo, const float* bo,
                          const float* wa, const float* ba,
                          const float* wb, const float* bb,
                          const float* ga, const float* bea,
                          const float* gb, const float* beb,
                          const float* __restrict__ Kp,
                          const float* __restrict__ Vp) {
    int tid  = threadIdx.x;
    int lane = tid & 31, warp = tid >> 5;
    int g  = lane >> 2, tg = lane & 3;
    int m0 = (warp & 3) * 16;
    int n0 = (warp >> 2) * 64;
    float* Tq = s->S;          // row-major 64 x TQS
    float c[8][4];

    // ---- 1. Q = X @ wq (two k-halves) -> Tq ----
    zc(c);
    stage_chunk(wq, 0, 0, DIM, s->W);
    gemm64_mma(s->XT, s->W, m0, n0, g, tg, c);
    stage_chunk(wq, 64, 0, DIM, s->W);
    gemm64_mma(s->XT + 64 * PAD, s->W, m0, n0, g, tg, c);
    #pragma unroll
    for (int j = 0; j < 8; ++j) {
        int na = n0 + 16 * tg + j;
        int nb = na + 8;
        Tq[(size_t)(m0 + g) * TQS + na]     = c[j][0];
        Tq[(size_t)(m0 + g) * TQS + nb]     = c[j][1];
        Tq[(size_t)(m0 + g + 8) * TQS + na] = c[j][2];
        Tq[(size_t)(m0 + g + 8) * TQS + nb] = c[j][3];
    }
    __syncthreads();   // Tq visible; W readers done

    // prefetch wo chunk 0 while attention gathers run
    issue_chunk(wo, 0, 0, DIM, s->W);

    // ---- 2. attention: 2 (node,head) units per thread; node = idx&63, h = idx>>6
    float4 o2[2][4];
    #pragma unroll
    for (int u = 0; u < 2; ++u) {
        #pragma unroll
        for (int t = 0; t < 4; ++t) o2[u][t] = make_float4(0.f, 0.f, 0.f, 0.f);
        int idx  = tid + u * NTHREADS;
        int node = idx & 63;
        int h    = idx >> 6;
        int gg   = base + node;
        if (gg < N_NODES) {
            const float* qs = Tq + node * TQS + h * 16;
            float q[16];
            #pragma unroll
            for (int t = 0; t < 4; ++t) {
                float4 q4 = *(const float4*)(qs + t * 4);
                q[4*t] = q4.x; q[4*t+1] = q4.y; q[4*t+2] = q4.z; q[4*t+3] = q4.w;
            }
            float dots[KNBR]; bool msk[KNBR];
            #pragma unroll
            for (int j = 0; j < KNBR; ++j) {
                int mflag = s->nmask[node * KNBR + j];
                msk[j] = (mflag != 0);
                if (mflag) { dots[j] = -1e30f; continue; }
                int nb = s->nidx[node * KNBR + j];
                const float4* kp = (const float4*)(Kp + (size_t)nb * DIM + h * 16);
                float d = 0.f;
                #pragma unroll
                for (int t = 0; t < 4; ++t) {
                    float4 k4 = kp[t];
                    d = fmaf(q[4*t+0], k4.x, d);
                    d = fmaf(q[4*t+1], k4.y, d);
                    d = fmaf(q[4*t+2], k4.z, d);
                    d = fmaf(q[4*t+3], k4.w, d);
                }
                dots[j] = d * 0.25f;
            }
            float mmax = -1e30f;
            #pragma unroll
            for (int j = 0; j < KNBR; ++j) mmax = fmaxf(mmax, dots[j]);
            float e[KNBR]; float ssum = 0.f;
            #pragma unroll
            for (int j = 0; j < KNBR; ++j) {
                e[j] = msk[j] ? 0.f : __expf(dots[j] - mmax);
                ssum += e[j];
            }
            float inv = 1.f / ssum;
            #pragma unroll
            for (int j = 0; j < KNBR; ++j) {
                if (!msk[j]) {
                    int nb = s->nidx[node * KNBR + j];
                    const float4* vp = (const float4*)(Vp + (size_t)nb * DIM + h * 16);
                    float a = e[j] * inv;
                    #pragma unroll
                    for (int t = 0; t < 4; ++t) {
                        float4 v4 = vp[t];
                        o2[u][t].x = fmaf(a, v4.x, o2[u][t].x);
                        o2[u][t].y = fmaf(a, v4.y, o2[u][t].y);
                        o2[u][t].z = fmaf(a, v4.z, o2[u][t].z);
                        o2[u][t].w = fmaf(a, v4.w, o2[u][t].w);
                    }
                }
            }
        }
    }
    __syncthreads();   // everyone finished reading Tq
    #pragma unroll
    for (int u = 0; u < 2; ++u) {
        int idx  = tid + u * NTHREADS;
        int node = idx & 63;
        int h    = idx >> 6;
        int pn   = (node + ((h & 3) << 3)) & 63;   // KROT(cc), cc>>4 == h
        #pragma unroll
        for (int t = 0; t < 4; ++t) {
            int cc = h * 16 + t * 4;
            s->S[(cc + 0) * PAD + pn] = o2[u][t].x;
            s->S[(cc + 1) * PAD + pn] = o2[u][t].y;
            s->S[(cc + 2) * PAD + pn] = o2[u][t].z;
            s->S[(cc + 3) * PAD + pn] = o2[u][t].w;
        }
    }
    cp_wait();
    __syncthreads();   // AT + wo chunk0 ready

    // ---- 3. U = attn @ wo + bo ----
    zc(c);
    gemm64_mma(s->S, s->W, m0, n0, g, tg, c);
    stage_chunk(wo, 64, 0, DIM, s->W);
    gemm64_mma(s->S + 64 * PAD, s->W, m0, n0, g, tg, c);
    __syncthreads();                 // all done reading AT (S)
    store_frag(s->S, bo, false, m0, n0, g, tg, c);   // U over AT
    issue_chunk(wa, 0, 0, 256, s->W);                // prefetch wa chunk0 during LN
    __syncthreads();                 // U visible

    // ---- 4. X = LN(X + U) ----
    ln_t(s->XT, s->S, ga, bea);
    cp_wait();
    __syncthreads();                 // LN'd XT + wa chunk0 ready

    // ---- 5. FFN H phase: H = relu(X @ wa + ba) -> g_H (both halves) ----
    #pragma unroll
    for (int h = 0; h < 2; ++h) {
        if (h == 1) stage_chunk(wa, 0, 128, 256, s->W);
        zc(c);
        gemm64_mma(s->XT, s->W, m0, n0, g, tg, c);
        stage_chunk(wa, 64, h * 128, 256, s->W);
        gemm64_mma(s->XT + 64 * PAD, s->W, m0, n0, g, tg, c);
        store_frag_gH(base, h * 128, ba + h * 128, m0, n0, g, tg, c);
    }

    // ---- 6. FFN F phase: F = H @ wb + bb, K=256 in two halves via S ----
    zc(c);
    #pragma unroll
    for (int h = 0; h < 2; ++h) {
        __syncthreads();             // S free (prior readers done); g_H writes visible
        for (int i = tid; i < BLOCK * 32; i += NTHREADS) {
            int node = i >> 5;
            int k4   = (i & 31) << 2;
            int gg   = base + node;
            float4 v = make_float4(0.f, 0.f, 0.f, 0.f);
            if (gg < N_NODES)
                v = *(const float4*)(g_H + (size_t)gg * 256 + h * 128 + k4);
            int pn = (node + KROT(k4)) & 63;
            s->S[(k4 + 0) * PAD + pn] = v.x;
            s->S[(k4 + 1) * PAD + pn] = v.y;
            s->S[(k4 + 2) * PAD + pn] = v.z;
            s->S[(k4 + 3) * PAD + pn] = v.w;
        }
        stage_chunk(wb, h * 128, 0, DIM, s->W);      // entry sync makes S visible
        gemm64_mma(s->S, s->W, m0, n0, g, tg, c);
        stage_chunk(wb, h * 128 + 64, 0, DIM, s->W);
        gemm64_mma(s->S + 64 * PAD, s->W, m0, n0, g, tg, c);
    }
    __syncthreads();                // all done reading H-half (S)
    store_frag(s->S, bb, false, m0, n0, g, tg, c);   // F
    __syncthreads();

    // ---- 7. X = LN(X + F) ----
    ln_t(s->XT, s->S, gb, beb);
    __syncthreads();
}

// ---------------- kernel 1: Kp/Vp projections + row sums ----------------
extern "C" __global__ void __launch_bounds__(NTHREADS, 3)
pre_kernel(const float* __restrict__ feat,
           const float* __restrict__ wk1, const float* __restrict__ wv1,
           const float* __restrict__ wk2, const float* __restrict__ wv2) {
    extern __shared__ char smem_raw[];
    SmemPre* s = (SmemPre*)smem_raw;
    int tid  = threadIdx.x;
    int base = blockIdx.x * BLOCK;

    #pragma unroll
    for (int i = tid; i < BLOCK * 32; i += NTHREADS) {
        int node = i >> 5;
        int k4   = (i & 31) << 2;
        int gg   = base + node;
        float4 v = make_float4(0.f, 0.f, 0.f, 0.f);
        if (gg < N_NODES) v = *(const float4*)(feat + (size_t)gg * DIM + k4);
        int pn = (node + KROT(k4)) & 63;
        s->XT[(k4 + 0) * PAD + pn] = v.x;
        s->XT[(k4 + 1) * PAD + pn] = v.y;
        s->XT[(k4 + 2) * PAD + pn] = v.z;
        s->XT[(k4 + 3) * PAD + pn] = v.w;
    }
    __syncthreads();

    {   // row sums (2 units per thread)
        #pragma unroll
        for (int u = 0; u < 2; ++u) {
            int idx  = tid + u * NTHREADS;
            int node = idx >> 3;
            int h    = idx & 7;
            float ssum = 0.f;
            #pragma unroll
            for (int i = 0; i < 16; ++i) {
                int e  = h + 8 * i;
                int pn = (node + (((i >> 1) & 3) << 3)) & 63;
                ssum += s->XT[e * PAD + pn];
            }
            ssum += __shfl_xor_sync(0xffffffffu, ssum, 1);
            ssum += __shfl_xor_sync(0xffffffffu, ssum, 2);
            ssum += __shfl_xor_sync(0xffffffffu, ssum, 4);
            int gg = base + node;
            if (h == 0 && gg < N_NODES) g_rowsum[gg] = ssum;
        }
    }

    int lane = tid & 31, warp = tid >> 5;
    int g  = lane >> 2, tg = lane & 3;
    int m0 = (warp & 3) * 16;
    int n0 = (warp >> 2) * 64;
    const float* ws_in[4] = {wk1, wv1, wk2, wv2};
    float* outs[4] = {g_Kp1, g_Vp1, g_Kp2, g_Vp2};
    float c[8][4];
    #pragma unroll
    for (int w = 0; w < 4; ++w) {
        zc(c);
        stage_chunk(ws_in[w], 0, 0, DIM, s->W);
        gemm64_mma(s->XT, s->W, m0, n0, g, tg, c);
        stage_chunk(ws_in[w], 64, 0, DIM, s->W);
        gemm64_mma(s->XT + 64 * PAD, s->W, m0, n0, g, tg, c);
        float* op = outs[w];
        int gm0 = base + m0 + g;
        int gm1 = gm0 + 8;
        int nb0 = n0 + 16 * tg;
        if (gm0 < N_NODES) {
            *(float4*)(op + (size_t)gm0 * DIM + nb0)      = make_float4(c[0][0], c[1][0], c[2][0], c[3][0]);
            *(float4*)(op + (size_t)gm0 * DIM + nb0 + 4)  = make_float4(c[4][0], c[5][0], c[6][0], c[7][0]);
            *(float4*)(op + (size_t)gm0 * DIM + nb0 + 8)  = make_float4(c[0][1], c[1][1], c[2][1], c[3][1]);
            *(float4*)(op + (size_t)gm0 * DIM + nb0 + 12) = make_float4(c[4][1], c[5][1], c[6][1], c[7][1]);
        }
        if (gm1 < N_NODES) {
            *(float4*)(op + (size_t)gm1 * DIM + nb0)      = make_float4(c[0][2], c[1][2], c[2][2], c[3][2]);
            *(float4*)(op + (size_t)gm1 * DIM + nb0 + 4)  = make_float4(c[4][2], c[5][2], c[6][2], c[7][2]);
            *(float4*)(op + (size_t)gm1 * DIM + nb0 + 8)  = make_float4(c[0][3], c[1][3], c[2][3], c[3][3]);
            *(float4*)(op + (size_t)gm1 * DIM + nb0 + 12) = make_float4(c[4][3], c[5][3], c[6][3], c[7][3]);
        }
    }
}

// ---------------- kernel 2: fused 2-layer transformer + head ----------------
extern "C" __global__ void __launch_bounds__(NTHREADS, 2)
main_kernel(const float* __restrict__ feat,
            const int* __restrict__ nbr_idx,
            const int* __restrict__ nbr_valid,
            const float* wq1, const float* wo1, const float* bo1,
            const float* w1a, const float* b1a, const float* w1b, const float* b1b,
            const float* g1a, const float* be1a, const float* g1b, const float* be1b,
            const float* wq2, const float* wo2, const float* bo2,
            const float* w2a, const float* b2a, const float* w2b, const float* b2b,
            const float* g2a, const float* be2a, const float* g2b, const float* be2b,
            const float* w4, const float* b4,
            float* __restrict__ out) {
    extern __shared__ char smem_raw[];
    SmemMain* s = (SmemMain*)smem_raw;
    int tid  = threadIdx.x;
    int base = blockIdx.x * BLOCK;

    #pragma unroll
    for (int i = tid; i < BLOCK * 32; i += NTHREADS) {
        int node = i >> 5;
        int k4   = (i & 31) << 2;
        int gg   = base + node;
        float4 v = make_float4(0.f, 0.f, 0.f, 0.f);
        if (gg < N_NODES) v = *(const float4*)(feat + (size_t)gg * DIM + k4);
        int pn = (node + KROT(k4)) & 63;
        s->XT[(k4 + 0) * PAD + pn] = v.x;
        s->XT[(k4 + 1) * PAD + pn] = v.y;
        s->XT[(k4 + 2) * PAD + pn] = v.z;
        s->XT[(k4 + 3) * PAD + pn] = v.w;
    }
    for (int i = tid; i < BLOCK * KNBR; i += NTHREADS) {
        int node = i / KNBR;
        int j    = i - node * KNBR;
        int gg   = base + node;
        int idx = 0, mflag = 1;
        if (gg < N_NODES) {
            idx = nbr_idx[(size_t)gg * KNBR + j];
            int valid = nbr_valid[(size_t)gg * KNBR + j];   // nonzero = true
            mflag = (valid == 0) || (g_rowsum[idx] == 0.f);
        }
        s->nidx[i]  = idx;
        s->nmask[i] = mflag;
    }
    __syncthreads();

    run_layer(s, base, wq1, wo1, bo1, w1a, b1a, w1b, b1b,
              g1a, be1a, g1b, be1b, g_Kp1, g_Vp1);
    run_layer(s, base, wq2, wo2, bo2, w2a, b2a, w2b, b2b,
              g2a, be2a, g2b, be2b, g_Kp2, g_Vp2);

    // ---- head: out = tanh(X @ w4 + b4), w4: 128x64 (row stride 64, unswizzled) --
    __syncthreads();
    {
        #pragma unroll
        for (int i = tid; i < 2048; i += NTHREADS) {   // 2048 float4
            int r  = i >> 4;
            int c4 = (i & 15) << 2;
            cp16(sptr(s->W + r * 64 + c4), w4 + r * 64 + c4);
        }
        cp_commit();
        cp_waitall();
    }
    __syncthreads();
    #pragma unroll
    for (int u = 0; u < 2; ++u) {
        int idx  = tid + u * NTHREADS;
        int node = idx >> 3;
        int c0   = (idx & 7) * 8;
        float acc8[8];
        #pragma unroll
        for (int c = 0; c < 8; ++c) acc8[c] = 0.f;
        #pragma unroll 4
        for (int kk = 0; kk < DIM; ++kk) {
            int pn = (node + KROT(kk)) & 63;
            float a = s->XT[kk * PAD + pn];
            float4 w0 = *(const float4*)(s->W + kk * 64 + c0);
            float4 w1 = *(const float4*)(s->W + kk * 64 + c0 + 4);
            acc8[0] = fmaf(a, w0.x, acc8[0]);
            acc8[1] = fmaf(a, w0.y, acc8[1]);
            acc8[2] = fmaf(a, w0.z, acc8[2]);
            acc8[3] = fmaf(a, w0.w, acc8[3]);
            acc8[4] = fmaf(a, w1.x, acc8[4]);
            acc8[5] = fmaf(a, w1.y, acc8[5]);
            acc8[6] = fmaf(a, w1.z, acc8[6]);
            acc8[7] = fmaf(a, w1.w, acc8[7]);
        }
        int gg = base + node;
        if (gg < N_NODES) {
            #pragma unroll
            for (int c = 0; c < 8; ++c)
                out[(size_t)gg * 64 + c0 + c] = tanhf(acc8[c] + b4[c0 + c]);
        }
    }
}

// ---------------- host launch ----------------
extern "C" void kernel_launch(void* const* d_in, const int* in_sizes, int n_in,
                              void* d_out, int out_size) {
    const float* feat  = (const float*)d_in[0];
    const int* nbr_idx = (const int*)d_in[1];
    const int* nbr_val = (const int*)d_in[2];
    const float* wq1 = (const float*)d_in[3];
    const float* wk1 = (const float*)d_in[4];
    const float* wv1 = (const float*)d_in[5];
    const float* wo1 = (const float*)d_in[6];
    const float* bo1 = (const float*)d_in[7];
    const float* w1a = (const float*)d_in[8];
    const float* b1a = (const float*)d_in[9];
    const float* w1b = (const float*)d_in[10];
    const float* b1b = (const float*)d_in[11];
    const float* g1a = (const float*)d_in[12];
    const float* be1a = (const float*)d_in[13];
    const float* g1b = (const float*)d_in[14];
    const float* be1b = (const float*)d_in[15];
    const float* wq2 = (const float*)d_in[16];
    const float* wk2 = (const float*)d_in[17];
    const float* wv2 = (const float*)d_in[18];
    const float* wo2 = (const float*)d_in[19];
    const float* bo2 = (const float*)d_in[20];
    const float* w2a = (const float*)d_in[21];
    const float* b2a = (const float*)d_in[22];
    const float* w2b = (const float*)d_in[23];
    const float* b2b = (const float*)d_in[24];
    const float* g2a = (const float*)d_in[25];
    const float* be2a = (const float*)d_in[26];
    const float* g2b = (const float*)d_in[27];
    const float* be2b = (const float*)d_in[28];
    const float* w4 = (const float*)d_in[29];
    const float* b4 = (const float*)d_in[30];
    float* out = (float*)d_out;

    cudaFuncSetAttribute(pre_kernel,  cudaFuncAttributeMaxDynamicSharedMemorySize,
                         (int)sizeof(SmemPre));
    cudaFuncSetAttribute(main_kernel, cudaFuncAttributeMaxDynamicSharedMemorySize,
                         (int)sizeof(SmemMain));

    pre_kernel<<<NTILES, NTHREADS, sizeof(SmemPre)>>>(feat, wk1, wv1, wk2, wv2);
    main_kernel<<<NTILES, NTHREADS, sizeof(SmemMain)>>>(
        feat, nbr_idx, nbr_val,
        wq1, wo1, bo1, w1a, b1a, w1b, b1b, g1a, be1a, g1b, be1b,
        wq2, wo2, bo2, w2a, b2a, w2b, b2b, g2a, be2a, g2b, be2b,
        w4, b4, out);
}

// round 16
// speedup vs baseline: 1.0473x; 1.0473x over previous
#include <cuda_runtime.h>
#include <cstdint>

#define N_NODES 300000
#define DIM 128
#define KNBR 5
#define EPS_LN 1e-5f
// pre kernel tile (64 nodes, 256 thr)
#define PBLOCK 64
#define PTHREADS 256
#define PTILES ((N_NODES + PBLOCK - 1) / PBLOCK)
#define PPAD 72
// main kernel tile (128 nodes, 512 thr)
#define MBLOCK 128
#define MTHREADS 512
#define MTILES ((N_NODES + MBLOCK - 1) / MBLOCK)
#define MPAD 136
#define TQS 132     // stride of row-major Q buffer
#define WS 132      // stride (floats) of weight smem rows

// k-major node rotation amount for row r
#define KROT(r) ((((r) >> 4) & 3) << 3)
// W column rotation: row r, col c lives at r*WS + ((c + WROT(r)) & 127)
#define WROT(r) (((r) & 2) << 2)

typedef unsigned long long ull;

// ---------------- global scratch ----------------
__device__ float g_Kp1[(size_t)N_NODES * DIM];
__device__ float g_Vp1[(size_t)N_NODES * DIM];
__device__ float g_Kp2[(size_t)N_NODES * DIM];
__device__ float g_Vp2[(size_t)N_NODES * DIM];
__device__ float g_rowsum[N_NODES];

// ---------------- helpers ----------------
__device__ __forceinline__ unsigned sptr(const void* p) {
    return (unsigned)__cvta_generic_to_shared(p);
}
__device__ __forceinline__ void cp16(unsigned saddr, const void* g) {
    asm volatile("cp.async.cg.shared.global [%0], [%1], 16;" :: "r"(saddr), "l"(g));
}
__device__ __forceinline__ void cp_commit() {
    asm volatile("cp.async.commit_group;" ::: "memory");
}
__device__ __forceinline__ void cp_waitall() {
    asm volatile("cp.async.wait_group 0;" ::: "memory");
}
__device__ __forceinline__ void cp_wait() {
    asm volatile("cp.async.commit_group;\n\tcp.async.wait_group 0;" ::: "memory");
}
__device__ __forceinline__ unsigned cvt_tf32(float x) {
    unsigned r;
    asm("cvt.rna.tf32.f32 %0, %1;" : "=r"(r) : "f"(x));
    return r;
}
// m16n8k8 tf32 mma: D = A@B + D (fp32 accum)
__device__ __forceinline__ void mma8(float c[4], unsigned a0, unsigned a1,
                                     unsigned a2, unsigned a3,
                                     unsigned b0, unsigned b1) {
    asm volatile(
        "mma.sync.aligned.m16n8k8.row.col.f32.tf32.tf32.f32 "
        "{%0,%1,%2,%3},{%4,%5,%6,%7},{%8,%9},{%0,%1,%2,%3};"
        : "+f"(c[0]), "+f"(c[1]), "+f"(c[2]), "+f"(c[3])
        : "r"(a0), "r"(a1), "r"(a2), "r"(a3), "r"(b0), "r"(b1));
}

// ---------------- shared memory layouts ----------------
struct SmemMain {
    float XT[DIM * MPAD];   // residual stream, k-major rotated (69632 B)
    float W[64 * WS];       // weight k-chunk, column-rotated   (33792 B)
    float S[DIM * MPAD];    // scratch: Tq | AT | U | H | F     (69632 B)
    int   nidx[MBLOCK * KNBR];
    int   nmask[MBLOCK * KNBR];
};                          // ~174 KB -> 1 CTA/SM (512 thr, 16 warps)
struct SmemPre {
    float XT[DIM * PPAD];
    float W[64 * WS];
};                          // ~69 KB -> 3 CTAs/SM

// ---------------- W chunk loaders (cp.async, 64 rows x 128 cols, stride WS) ----
template<int NT>
__device__ __forceinline__ void issue_chunk(const float* __restrict__ Wg,
                                            int row0, int col0, int ncols,
                                            float* __restrict__ Ws) {
    int tid = threadIdx.x;
    #pragma unroll
    for (int i = tid; i < 2048; i += NT) {   // 2048 float4
        int r  = i >> 5;
        int c4 = (i & 31) << 2;
        int pc = (c4 + WROT(r)) & 127;       // column rotation
        cp16(sptr(Ws + r * WS + pc),
             Wg + (size_t)(row0 + r) * ncols + col0 + c4);
    }
}
template<int NT>
__device__ __forceinline__ void stage_chunk(const float* __restrict__ Wg,
                                            int row0, int col0, int ncols,
                                            float* __restrict__ Ws) {
    __syncthreads();
    issue_chunk<NT>(Wg, row0, col0, ncols, Ws);
    cp_wait();
    __syncthreads();
}

__device__ __forceinline__ void zc(float c[8][4]) {
    #pragma unroll
    for (int j = 0; j < 8; ++j)
        #pragma unroll
        for (int i = 0; i < 4; ++i) c[j][i] = 0.f;
}

// C[.. x128] += A(k-major rotated, stride APAD, node mask AMASK) @ W(col-rotated)
template<int APAD, int AMASK>
__device__ __forceinline__ void gemm64_mma(const float* __restrict__ A,
                                           const float* __restrict__ W,
                                           int m0, int n0, int g, int tg,
                                           float c[8][4]) {
    #pragma unroll
    for (int ks = 0; ks < 8; ++ks) {
        int r    = ks * 8 + tg;
        int rot  = ((ks >> 1) & 3) << 3;           // KROT(r), lane-invariant
        const float* ar = A + r * APAD;
        int p0 = (m0 + g + rot) & AMASK;
        int p1 = (m0 + g + 8 + rot) & AMASK;
        unsigned a0 = cvt_tf32(ar[p0]);
        unsigned a1 = cvt_tf32(ar[p1]);
        unsigned a2 = cvt_tf32(ar[4 * APAD + p0]);
        unsigned a3 = cvt_tf32(ar[4 * APAD + p1]);
        int wrot = (tg & 2) << 2;                  // WROT(r), r&2 == tg&2
        const float* wr = W + r * WS;
        int cb0 = (n0 + 8 * g + wrot) & 127;
        int cb1 = (n0 + 8 * g + 4 + wrot) & 127;
        float4 b0a = *(const float4*)(wr + cb0);
        float4 b0b = *(const float4*)(wr + cb1);
        float4 b1a = *(const float4*)(wr + 4 * WS + cb0);
        float4 b1b = *(const float4*)(wr + 4 * WS + cb1);
        float b0v[8] = {b0a.x, b0a.y, b0a.z, b0a.w, b0b.x, b0b.y, b0b.z, b0b.w};
        float b1v[8] = {b1a.x, b1a.y, b1a.z, b1a.w, b1b.x, b1b.y, b1b.z, b1b.w};
        #pragma unroll
        for (int j = 0; j < 8; ++j)
            mma8(c[j], a0, a1, a2, a3,
                 __float_as_uint(b0v[j]), __float_as_uint(b1v[j]));
    }
}

// store C frags to k-major rotated buffer with bias (+optional relu)
template<int APAD, int AMASK>
__device__ __forceinline__ void store_frag(float* __restrict__ Dst,
                                           const float* __restrict__ bias,
                                           bool relu, int m0, int n0,
                                           int g, int tg, const float c[8][4]) {
    int rot = tg << 3;
    int pm0 = (m0 + g + rot) & AMASK;
    int pm1 = (m0 + g + 8 + rot) & AMASK;
    #pragma unroll
    for (int j = 0; j < 8; ++j) {
        int na = n0 + 16 * tg + j;
        int nb = na + 8;
        float ba_ = bias[na], bb_ = bias[nb];
        float v0 = c[j][0] + ba_, v1 = c[j][1] + bb_;
        float v2 = c[j][2] + ba_, v3 = c[j][3] + bb_;
        if (relu) {
            v0 = fmaxf(v0, 0.f); v1 = fmaxf(v1, 0.f);
            v2 = fmaxf(v2, 0.f); v3 = fmaxf(v3, 0.f);
        }
        Dst[(size_t)na * APAD + pm0] = v0;
        Dst[(size_t)nb * APAD + pm0] = v1;
        Dst[(size_t)na * APAD + pm1] = v2;
        Dst[(size_t)nb * APAD + pm1] = v3;
    }
}

// LN: XT = LN(XT + UT)*gamma + beta (both k-major rotated). 2 units per thread.
template<int APAD, int AMASK, int NT>
__device__ __forceinline__ void ln_t(float* __restrict__ XT,
                                     const float* __restrict__ UT,
                                     const float* __restrict__ gamma,
                                     const float* __restrict__ beta) {
    int tid = threadIdx.x;
    #pragma unroll
    for (int u = 0; u < 2; ++u) {
        int idx  = tid + u * NT;
        int node = idx >> 3;
        int h    = idx & 7;
        float v[16];
        float sum = 0.f;
        #pragma unroll
        for (int i = 0; i < 16; ++i) {
            int e  = h + 8 * i;
            int pn = (node + (((i >> 1) & 3) << 3)) & AMASK;   // KROT(e)
            v[i] = XT[e * APAD + pn] + UT[e * APAD + pn];
            sum += v[i];
        }
        sum += __shfl_xor_sync(0xffffffffu, sum, 1);
        sum += __shfl_xor_sync(0xffffffffu, sum, 2);
        sum += __shfl_xor_sync(0xffffffffu, sum, 4);
        float m = sum * (1.f / 128.f);
        float sq = 0.f;
        #pragma unroll
        for (int i = 0; i < 16; ++i) { float d = v[i] - m; sq = fmaf(d, d, sq); }
        sq += __shfl_xor_sync(0xffffffffu, sq, 1);
        sq += __shfl_xor_sync(0xffffffffu, sq, 2);
        sq += __shfl_xor_sync(0xffffffffu, sq, 4);
        float inv = rsqrtf(sq * (1.f / 128.f) + EPS_LN);
        #pragma unroll
        for (int i = 0; i < 16; ++i) {
            int e  = h + 8 * i;
            int pn = (node + (((i >> 1) & 3) << 3)) & AMASK;
            XT[e * APAD + pn] = (v[i] - m) * inv * gamma[e] + beta[e];
        }
    }
}

// ---------------- one transformer layer (main, 128-node tile) ----------------
__device__ void run_layer(SmemMain* s, int base,
                          const float* wq, const float* wo, const float* bo,
                          const float* wa, const float* ba,
                          const float* wb, const float* bb,
                          const float* ga, const float* bea,
                          const float* gb, const float* beb,
                          const float* __restrict__ Kp,
                          const float* __restrict__ Vp) {
    int tid  = threadIdx.x;
    int lane = tid & 31, warp = tid >> 5;
    int g  = lane >> 2, tg = lane & 3;
    int m0 = (warp & 7) * 16;      // 0..112
    int n0 = (warp >> 3) * 64;     // 0 or 64
    float* Tq = s->S;              // row-major 128 x TQS
    float c[8][4];

    // ---- 1. Q = X @ wq (two k-halves) -> Tq ----
    zc(c);
    stage_chunk<MTHREADS>(wq, 0, 0, DIM, s->W);
    gemm64_mma<MPAD, 127>(s->XT, s->W, m0, n0, g, tg, c);
    stage_chunk<MTHREADS>(wq, 64, 0, DIM, s->W);
    gemm64_mma<MPAD, 127>(s->XT + 64 * MPAD, s->W, m0, n0, g, tg, c);
    #pragma unroll
    for (int j = 0; j < 8; ++j) {
        int na = n0 + 16 * tg + j;
        int nb = na + 8;
        Tq[(size_t)(m0 + g) * TQS + na]     = c[j][0];
        Tq[(size_t)(m0 + g) * TQS + nb]     = c[j][1];
        Tq[(size_t)(m0 + g + 8) * TQS + na] = c[j][2];
        Tq[(size_t)(m0 + g + 8) * TQS + nb] = c[j][3];
    }
    __syncthreads();   // Tq visible; W readers done

    // prefetch wo chunk 0 while attention gathers run
    issue_chunk<MTHREADS>(wo, 0, 0, DIM, s->W);

    // ---- 2. attention: 2 (node,head) units per thread; node = idx&127, h = idx>>7
    float4 o2[2][4];
    #pragma unroll
    for (int u = 0; u < 2; ++u) {
        #pragma unroll
        for (int t = 0; t < 4; ++t) o2[u][t] = make_float4(0.f, 0.f, 0.f, 0.f);
        int idx  = tid + u * MTHREADS;
        int node = idx & 127;
        int h    = idx >> 7;
        int gg   = base + node;
        if (gg < N_NODES) {
            const float* qs = Tq + node * TQS + h * 16;
            float q[16];
            #pragma unroll
            for (int t = 0; t < 4; ++t) {
                float4 q4 = *(const float4*)(qs + t * 4);
                q[4*t] = q4.x; q[4*t+1] = q4.y; q[4*t+2] = q4.z; q[4*t+3] = q4.w;
            }
            float dots[KNBR]; bool msk[KNBR];
            #pragma unroll
            for (int j = 0; j < KNBR; ++j) {
                int mflag = s->nmask[node * KNBR + j];
                msk[j] = (mflag != 0);
                if (mflag) { dots[j] = -1e30f; continue; }
                int nb = s->nidx[node * KNBR + j];
                const float4* kp = (const float4*)(Kp + (size_t)nb * DIM + h * 16);
                float d = 0.f;
                #pragma unroll
                for (int t = 0; t < 4; ++t) {
                    float4 k4 = kp[t];
                    d = fmaf(q[4*t+0], k4.x, d);
                    d = fmaf(q[4*t+1], k4.y, d);
                    d = fmaf(q[4*t+2], k4.z, d);
                    d = fmaf(q[4*t+3], k4.w, d);
                }
                dots[j] = d * 0.25f;
            }
            float mmax = -1e30f;
            #pragma unroll
            for (int j = 0; j < KNBR; ++j) mmax = fmaxf(mmax, dots[j]);
            float e[KNBR]; float ssum = 0.f;
            #pragma unroll
            for (int j = 0; j < KNBR; ++j) {
                e[j] = msk[j] ? 0.f : __expf(dots[j] - mmax);
                ssum += e[j];
            }
            float inv = 1.f / ssum;
            #pragma unroll
            for (int j = 0; j < KNBR; ++j) {
                if (!msk[j]) {
                    int nb = s->nidx[node * KNBR + j];
                    const float4* vp = (const float4*)(Vp + (size_t)nb * DIM + h * 16);
                    float a = e[j] * inv;
                    #pragma unroll
                    for (int t = 0; t < 4; ++t) {
                        float4 v4 = vp[t];
                        o2[u][t].x = fmaf(a, v4.x, o2[u][t].x);
                        o2[u][t].y = fmaf(a, v4.y, o2[u][t].y);
                        o2[u][t].z = fmaf(a, v4.z, o2[u][t].z);
                        o2[u][t].w = fmaf(a, v4.w, o2[u][t].w);
                    }
                }
            }
        }
    }
    __syncthreads();   // everyone finished reading Tq
    #pragma unroll
    for (int u = 0; u < 2; ++u) {
        int idx  = tid + u * MTHREADS;
        int node = idx & 127;
        int h    = idx >> 7;
        int pn   = (node + ((h & 3) << 3)) & 127;   // KROT(cc), cc>>4 == h
        #pragma unroll
        for (int t = 0; t < 4; ++t) {
            int cc = h * 16 + t * 4;
            s->S[(cc + 0) * MPAD + pn] = o2[u][t].x;
            s->S[(cc + 1) * MPAD + pn] = o2[u][t].y;
            s->S[(cc + 2) * MPAD + pn] = o2[u][t].z;
            s->S[(cc + 3) * MPAD + pn] = o2[u][t].w;
        }
    }
    cp_wait();
    __syncthreads();   // AT + wo chunk0 ready

    // ---- 3. U = attn @ wo + bo ----
    zc(c);
    gemm64_mma<MPAD, 127>(s->S, s->W, m0, n0, g, tg, c);
    stage_chunk<MTHREADS>(wo, 64, 0, DIM, s->W);
    gemm64_mma<MPAD, 127>(s->S + 64 * MPAD, s->W, m0, n0, g, tg, c);
    __syncthreads();                 // all done reading AT (S)
    store_frag<MPAD, 127>(s->S, bo, false, m0, n0, g, tg, c);   // U over AT
    issue_chunk<MTHREADS>(wa, 0, 0, 256, s->W);   // prefetch wa chunk0 during LN
    __syncthreads();                 // U visible

    // ---- 4. X = LN(X + U) ----
    ln_t<MPAD, 127, MTHREADS>(s->XT, s->S, ga, bea);
    cp_wait();
    __syncthreads();                 // LN'd XT + wa chunk0 ready

    // ---- 5/6. FFN: per output-half, H-half -> cF ----
    float cF[8][4]; zc(cF);
    #pragma unroll
    for (int h = 0; h < 2; ++h) {
        zc(c);
        if (h == 1) stage_chunk<MTHREADS>(wa, 0, 128, 256, s->W);
        gemm64_mma<MPAD, 127>(s->XT, s->W, m0, n0, g, tg, c);
        stage_chunk<MTHREADS>(wa, 64, h * 128, 256, s->W);
        gemm64_mma<MPAD, 127>(s->XT + 64 * MPAD, s->W, m0, n0, g, tg, c);
        __syncthreads();            // prior S readers done
        store_frag<MPAD, 127>(s->S, ba + h * 128, true, m0, n0, g, tg, c);  // H-half
        __syncthreads();
        stage_chunk<MTHREADS>(wb, h * 128, 0, DIM, s->W);
        gemm64_mma<MPAD, 127>(s->S, s->W, m0, n0, g, tg, cF);
        stage_chunk<MTHREADS>(wb, h * 128 + 64, 0, DIM, s->W);
        gemm64_mma<MPAD, 127>(s->S + 64 * MPAD, s->W, m0, n0, g, tg, cF);
    }
    __syncthreads();                // all done reading H (S)
    store_frag<MPAD, 127>(s->S, bb, false, m0, n0, g, tg, cF);  // F
    __syncthreads();

    // ---- 7. X = LN(X + F) ----
    ln_t<MPAD, 127, MTHREADS>(s->XT, s->S, gb, beb);
    __syncthreads();
}

// ---------------- kernel 1: Kp/Vp projections + row sums (round-14 winner) ----
extern "C" __global__ void __launch_bounds__(PTHREADS, 3)
pre_kernel(const float* __restrict__ feat,
           const float* __restrict__ wk1, const float* __restrict__ wv1,
           const float* __restrict__ wk2, const float* __restrict__ wv2) {
    extern __shared__ char smem_raw[];
    SmemPre* s = (SmemPre*)smem_raw;
    int tid  = threadIdx.x;
    int base = blockIdx.x * PBLOCK;

    #pragma unroll
    for (int i = tid; i < PBLOCK * 32; i += PTHREADS) {
        int node = i >> 5;
        int k4   = (i & 31) << 2;
        int gg   = base + node;
        float4 v = make_float4(0.f, 0.f, 0.f, 0.f);
        if (gg < N_NODES) v = *(const float4*)(feat + (size_t)gg * DIM + k4);
        int pn = (node + KROT(k4)) & 63;
        s->XT[(k4 + 0) * PPAD + pn] = v.x;
        s->XT[(k4 + 1) * PPAD + pn] = v.y;
        s->XT[(k4 + 2) * PPAD + pn] = v.z;
        s->XT[(k4 + 3) * PPAD + pn] = v.w;
    }
    __syncthreads();

    {   // row sums (2 units per thread)
        #pragma unroll
        for (int u = 0; u < 2; ++u) {
            int idx  = tid + u * PTHREADS;
            int node = idx >> 3;
            int h    = idx & 7;
            float ssum = 0.f;
            #pragma unroll
            for (int i = 0; i < 16; ++i) {
                int e  = h + 8 * i;
                int pn = (node + (((i >> 1) & 3) << 3)) & 63;
                ssum += s->XT[e * PPAD + pn];
            }
            ssum += __shfl_xor_sync(0xffffffffu, ssum, 1);
            ssum += __shfl_xor_sync(0xffffffffu, ssum, 2);
            ssum += __shfl_xor_sync(0xffffffffu, ssum, 4);
            int gg = base + node;
            if (h == 0 && gg < N_NODES) g_rowsum[gg] = ssum;
        }
    }

    int lane = tid & 31, warp = tid >> 5;
    int g  = lane >> 2, tg = lane & 3;
    int m0 = (warp & 3) * 16;
    int n0 = (warp >> 2) * 64;
    const float* ws_in[4] = {wk1, wv1, wk2, wv2};
    float* outs[4] = {g_Kp1, g_Vp1, g_Kp2, g_Vp2};
    float c[8][4];
    #pragma unroll
    for (int w = 0; w < 4; ++w) {
        zc(c);
        stage_chunk<PTHREADS>(ws_in[w], 0, 0, DIM, s->W);
        gemm64_mma<PPAD, 63>(s->XT, s->W, m0, n0, g, tg, c);
        stage_chunk<PTHREADS>(ws_in[w], 64, 0, DIM, s->W);
        gemm64_mma<PPAD, 63>(s->XT + 64 * PPAD, s->W, m0, n0, g, tg, c);
        float* op = outs[w];
        int gm0 = base + m0 + g;
        int gm1 = gm0 + 8;
        int nb0 = n0 + 16 * tg;
        if (gm0 < N_NODES) {
            *(float4*)(op + (size_t)gm0 * DIM + nb0)      = make_float4(c[0][0], c[1][0], c[2][0], c[3][0]);
            *(float4*)(op + (size_t)gm0 * DIM + nb0 + 4)  = make_float4(c[4][0], c[5][0], c[6][0], c[7][0]);
            *(float4*)(op + (size_t)gm0 * DIM + nb0 + 8)  = make_float4(c[0][1], c[1][1], c[2][1], c[3][1]);
            *(float4*)(op + (size_t)gm0 * DIM + nb0 + 12) = make_float4(c[4][1], c[5][1], c[6][1], c[7][1]);
        }
        if (gm1 < N_NODES) {
            *(float4*)(op + (size_t)gm1 * DIM + nb0)      = make_float4(c[0][2], c[1][2], c[2][2], c[3][2]);
            *(float4*)(op + (size_t)gm1 * DIM + nb0 + 4)  = make_float4(c[4][2], c[5][2], c[6][2], c[7][2]);
            *(float4*)(op + (size_t)gm1 * DIM + nb0 + 8)  = make_float4(c[0][3], c[1][3], c[2][3], c[3][3]);
            *(float4*)(op + (size_t)gm1 * DIM + nb0 + 12) = make_float4(c[4][3], c[5][3], c[6][3], c[7][3]);
        }
    }
}

// ---------------- kernel 2: fused 2-layer transformer + head (128-node tiles) --
extern "C" __global__ void __launch_bounds__(MTHREADS, 1)
main_kernel(const float* __restrict__ feat,
            const int* __restrict__ nbr_idx,
            const int* __restrict__ nbr_valid,
            const float* wq1, const float* wo1, const float* bo1,
            const float* w1a, const float* b1a, const float* w1b, const float* b1b,
            const float* g1a, const float* be1a, const float* g1b, const float* be1b,
            const float* wq2, const float* wo2, const float* bo2,
            const float* w2a, const float* b2a, const float* w2b, const float* b2b,
            const float* g2a, const float* be2a, const float* g2b, const float* be2b,
            const float* w4, const float* b4,
            float* __restrict__ out) {
    extern __shared__ char smem_raw[];
    SmemMain* s = (SmemMain*)smem_raw;
    int tid  = threadIdx.x;
    int base = blockIdx.x * MBLOCK;

    #pragma unroll
    for (int i = tid; i < MBLOCK * 32; i += MTHREADS) {
        int node = i >> 5;
        int k4   = (i & 31) << 2;
        int gg   = base + node;
        float4 v = make_float4(0.f, 0.f, 0.f, 0.f);
        if (gg < N_NODES) v = *(const float4*)(feat + (size_t)gg * DIM + k4);
        int pn = (node + KROT(k4)) & 127;
        s->XT[(k4 + 0) * MPAD + pn] = v.x;
        s->XT[(k4 + 1) * MPAD + pn] = v.y;
        s->XT[(k4 + 2) * MPAD + pn] = v.z;
        s->XT[(k4 + 3) * MPAD + pn] = v.w;
    }
    for (int i = tid; i < MBLOCK * KNBR; i += MTHREADS) {
        int node = i / KNBR;
        int j    = i - node * KNBR;
        int gg   = base + node;
        int idx = 0, mflag = 1;
        if (gg < N_NODES) {
            idx = nbr_idx[(size_t)gg * KNBR + j];
            int valid = nbr_valid[(size_t)gg * KNBR + j];   // nonzero = true
            mflag = (valid == 0) || (g_rowsum[idx] == 0.f);
        }
        s->nidx[i]  = idx;
        s->nmask[i] = mflag;
    }
    __syncthreads();

    run_layer(s, base, wq1, wo1, bo1, w1a, b1a, w1b, b1b,
              g1a, be1a, g1b, be1b, g_Kp1, g_Vp1);
    run_layer(s, base, wq2, wo2, bo2, w2a, b2a, w2b, b2b,
              g2a, be2a, g2b, be2b, g_Kp2, g_Vp2);

    // ---- head: out = tanh(X @ w4 + b4), w4: 128x64 (row stride 64, unswizzled) --
    __syncthreads();
    {
        #pragma unroll
        for (int i = tid; i < 2048; i += MTHREADS) {   // 2048 float4
            int r  = i >> 4;
            int c4 = (i & 15) << 2;
            cp16(sptr(s->W + r * 64 + c4), w4 + r * 64 + c4);
        }
        cp_commit();
        cp_waitall();
    }
    __syncthreads();
    #pragma unroll
    for (int u = 0; u < 2; ++u) {
        int idx  = tid + u * MTHREADS;
        int node = idx >> 3;
        int c0   = (idx & 7) * 8;
        float acc8[8];
        #pragma unroll
        for (int c = 0; c < 8; ++c) acc8[c] = 0.f;
        #pragma unroll 4
        for (int kk = 0; kk < DIM; ++kk) {
            int pn = (node + KROT(kk)) & 127;
            float a = s->XT[kk * MPAD + pn];
            float4 w0 = *(const float4*)(s->W + kk * 64 + c0);
            float4 w1 = *(const float4*)(s->W + kk * 64 + c0 + 4);
            acc8[0] = fmaf(a, w0.x, acc8[0]);
            acc8[1] = fmaf(a, w0.y, acc8[1]);
            acc8[2] = fmaf(a, w0.z, acc8[2]);
            acc8[3] = fmaf(a, w0.w, acc8[3]);
            acc8[4] = fmaf(a, w1.x, acc8[4]);
            acc8[5] = fmaf(a, w1.y, acc8[5]);
            acc8[6] = fmaf(a, w1.z, acc8[6]);
            acc8[7] = fmaf(a, w1.w, acc8[7]);
        }
        int gg = base + node;
        if (gg < N_NODES) {
            #pragma unroll
            for (int c = 0; c < 8; ++c)
                out[(size_t)gg * 64 + c0 + c] = tanhf(acc8[c] + b4[c0 + c]);
        }
    }
}

// ---------------- host launch ----------------
extern "C" void kernel_launch(void* const* d_in, const int* in_sizes, int n_in,
                              void* d_out, int out_size) {
    const float* feat  = (const float*)d_in[0];
    const int* nbr_idx = (const int*)d_in[1];
    const int* nbr_val = (const int*)d_in[2];
    const float* wq1 = (const float*)d_in[3];
    const float* wk1 = (const float*)d_in[4];
    const float* wv1 = (const float*)d_in[5];
    const float* wo1 = (const float*)d_in[6];
    const float* bo1 = (const float*)d_in[7];
    const float* w1a = (const float*)d_in[8];
    const float* b1a = (const float*)d_in[9];
    const float* w1b = (const float*)d_in[10];
    const float* b1b = (const float*)d_in[11];
    const float* g1a = (const float*)d_in[12];
    const float* be1a = (const float*)d_in[13];
    const float* g1b = (const float*)d_in[14];
    const float* be1b = (const float*)d_in[15];
    const float* wq2 = (const float*)d_in[16];
    const float* wk2 = (const float*)d_in[17];
    const float* wv2 = (const float*)d_in[18];
    const float* wo2 = (const float*)d_in[19];
    const float* bo2 = (const float*)d_in[20];
    const float* w2a = (const float*)d_in[21];
    const float* b2a = (const float*)d_in[22];
    const float* w2b = (const float*)d_in[23];
    const float* b2b = (const float*)d_in[24];
    const float* g2a = (const float*)d_in[25];
    const float* be2a = (const float*)d_in[26];
    const float* g2b = (const float*)d_in[27];
    const float* be2b = (const float*)d_in[28];
    const float* w4 = (const float*)d_in[29];
    const float* b4 = (const float*)d_in[30];
    float* out = (float*)d_out;

    cudaFuncSetAttribute(pre_kernel,  cudaFuncAttributeMaxDynamicSharedMemorySize,
                         (int)sizeof(SmemPre));
    cudaFuncSetAttribute(main_kernel, cudaFuncAttributeMaxDynamicSharedMemorySize,
                         (int)sizeof(SmemMain));

    pre_kernel<<<PTILES, PTHREADS, sizeof(SmemPre)>>>(feat, wk1, wv1, wk2, wv2);
    main_kernel<<<MTILES, MTHREADS, sizeof(SmemMain)>>>(
        feat, nbr_idx, nbr_val,
        wq1, wo1, bo1, w1a, b1a, w1b, b1b, g1a, be1a, g1b, be1b,
        wq2, wo2, bo2, w2a, b2a, w2b, b2b, g2a, be2a, g2b, be2b,
        w4, b4, out);
}

// round 17
// speedup vs baseline: 1.1294x; 1.0784x over previous
#include <cuda_runtime.h>
#include <cstdint>

#define N_NODES 300000
#define DIM 128
#define KNBR 5
#define EPS_LN 1e-5f
// pre kernel tile (64 nodes, 256 thr)
#define PBLOCK 64
#define PTHREADS 256
#define PTILES ((N_NODES + PBLOCK - 1) / PBLOCK)
#define PPAD 72
// main kernel tile (128 nodes, 512 thr)
#define MBLOCK 128
#define MTHREADS 512
#define MTILES ((N_NODES + MBLOCK - 1) / MBLOCK)
#define MPAD 136
#define TQS 140     // stride of row-major Q buffer (conflict-free q-loads, warp=4n x 8h)
#define WS 132      // stride (floats) of weight smem rows

// k-major node rotation amount for row r
#define KROT(r) ((((r) >> 4) & 3) << 3)
// W column rotation: row r, col c lives at r*WS + ((c + WROT(r)) & 127)
#define WROT(r) (((r) & 2) << 2)

typedef unsigned long long ull;

// ---------------- global scratch ----------------
__device__ float g_Kp1[(size_t)N_NODES * DIM];
__device__ float g_Vp1[(size_t)N_NODES * DIM];
__device__ float g_Kp2[(size_t)N_NODES * DIM];
__device__ float g_Vp2[(size_t)N_NODES * DIM];
__device__ float g_rowsum[N_NODES];

// ---------------- helpers ----------------
__device__ __forceinline__ unsigned sptr(const void* p) {
    return (unsigned)__cvta_generic_to_shared(p);
}
__device__ __forceinline__ void cp16(unsigned saddr, const void* g) {
    asm volatile("cp.async.cg.shared.global [%0], [%1], 16;" :: "r"(saddr), "l"(g));
}
__device__ __forceinline__ void cp_commit() {
    asm volatile("cp.async.commit_group;" ::: "memory");
}
__device__ __forceinline__ void cp_waitall() {
    asm volatile("cp.async.wait_group 0;" ::: "memory");
}
__device__ __forceinline__ void cp_wait() {
    asm volatile("cp.async.commit_group;\n\tcp.async.wait_group 0;" ::: "memory");
}
__device__ __forceinline__ unsigned cvt_tf32(float x) {
    unsigned r;
    asm("cvt.rna.tf32.f32 %0, %1;" : "=r"(r) : "f"(x));
    return r;
}
// m16n8k8 tf32 mma: D = A@B + D (fp32 accum)
__device__ __forceinline__ void mma8(float c[4], unsigned a0, unsigned a1,
                                     unsigned a2, unsigned a3,
                                     unsigned b0, unsigned b1) {
    asm volatile(
        "mma.sync.aligned.m16n8k8.row.col.f32.tf32.tf32.f32 "
        "{%0,%1,%2,%3},{%4,%5,%6,%7},{%8,%9},{%0,%1,%2,%3};"
        : "+f"(c[0]), "+f"(c[1]), "+f"(c[2]), "+f"(c[3])
        : "r"(a0), "r"(a1), "r"(a2), "r"(a3), "r"(b0), "r"(b1));
}

// ---------------- shared memory layouts ----------------
struct SmemMain {
    float XT[DIM * MPAD];   // residual stream, k-major rotated (69632 B)
    float W[128 * WS];      // FULL weight 128x128, column-rotated (67584 B)
    float S[DIM * TQS];     // scratch: Tq(128xTQS) | k-major views use stride MPAD
    int   nidx[MBLOCK * KNBR];
    int   nmask[MBLOCK * KNBR];
};                          // ~209 KB -> 1 CTA/SM (512 thr, 16 warps)
struct SmemPre {
    float XT[DIM * PPAD];
    float W[64 * WS];
};                          // ~69 KB -> 3 CTAs/SM

// ---------------- full-weight loader (cp.async, 128 rows x 128 cols) ----------
template<int NT>
__device__ __forceinline__ void issue_full(const float* __restrict__ Wg,
                                           int row0, int col0, int ncols,
                                           float* __restrict__ Ws) {
    int tid = threadIdx.x;
    #pragma unroll
    for (int i = tid; i < 4096; i += NT) {   // 4096 float4
        int r  = i >> 5;
        int c4 = (i & 31) << 2;
        int pc = (c4 + WROT(r)) & 127;
        cp16(sptr(Ws + r * WS + pc),
             Wg + (size_t)(row0 + r) * ncols + col0 + c4);
    }
}
template<int NT>
__device__ __forceinline__ void stage_full(const float* __restrict__ Wg,
                                           int row0, int col0, int ncols,
                                           float* __restrict__ Ws) {
    __syncthreads();
    issue_full<NT>(Wg, row0, col0, ncols, Ws);
    cp_wait();
    __syncthreads();
}
// 64-row chunk loader for pre_kernel
template<int NT>
__device__ __forceinline__ void issue_chunk(const float* __restrict__ Wg,
                                            int row0, int col0, int ncols,
                                            float* __restrict__ Ws) {
    int tid = threadIdx.x;
    #pragma unroll
    for (int i = tid; i < 2048; i += NT) {
        int r  = i >> 5;
        int c4 = (i & 31) << 2;
        int pc = (c4 + WROT(r)) & 127;
        cp16(sptr(Ws + r * WS + pc),
             Wg + (size_t)(row0 + r) * ncols + col0 + c4);
    }
}
template<int NT>
__device__ __forceinline__ void stage_chunk(const float* __restrict__ Wg,
                                            int row0, int col0, int ncols,
                                            float* __restrict__ Ws) {
    __syncthreads();
    issue_chunk<NT>(Wg, row0, col0, ncols, Ws);
    cp_wait();
    __syncthreads();
}

__device__ __forceinline__ void zc(float c[8][4]) {
    #pragma unroll
    for (int j = 0; j < 8; ++j)
        #pragma unroll
        for (int i = 0; i < 4; ++i) c[j][i] = 0.f;
}

// C += A(k-major rotated, stride APAD, mask AMASK) @ W(col-rotated), K = KS*8
template<int APAD, int AMASK, int KS>
__device__ __forceinline__ void gemm_mma(const float* __restrict__ A,
                                         const float* __restrict__ W,
                                         int m0, int n0, int g, int tg,
                                         float c[8][4]) {
    #pragma unroll
    for (int ks = 0; ks < KS; ++ks) {
        int r    = ks * 8 + tg;
        int rot  = ((ks >> 1) & 3) << 3;           // KROT(r), lane-invariant
        const float* ar = A + r * APAD;
        int p0 = (m0 + g + rot) & AMASK;
        int p1 = (m0 + g + 8 + rot) & AMASK;
        unsigned a0 = cvt_tf32(ar[p0]);
        unsigned a1 = cvt_tf32(ar[p1]);
        unsigned a2 = cvt_tf32(ar[4 * APAD + p0]);
        unsigned a3 = cvt_tf32(ar[4 * APAD + p1]);
        int wrot = (tg & 2) << 2;                  // WROT(r), r&2 == tg&2
        const float* wr = W + r * WS;
        int cb0 = (n0 + 8 * g + wrot) & 127;
        int cb1 = (n0 + 8 * g + 4 + wrot) & 127;
        float4 b0a = *(const float4*)(wr + cb0);
        float4 b0b = *(const float4*)(wr + cb1);
        float4 b1a = *(const float4*)(wr + 4 * WS + cb0);
        float4 b1b = *(const float4*)(wr + 4 * WS + cb1);
        float b0v[8] = {b0a.x, b0a.y, b0a.z, b0a.w, b0b.x, b0b.y, b0b.z, b0b.w};
        float b1v[8] = {b1a.x, b1a.y, b1a.z, b1a.w, b1b.x, b1b.y, b1b.z, b1b.w};
        #pragma unroll
        for (int j = 0; j < 8; ++j)
            mma8(c[j], a0, a1, a2, a3,
                 __float_as_uint(b0v[j]), __float_as_uint(b1v[j]));
    }
}

// store C frags to k-major rotated buffer with bias (+optional relu)
template<int APAD, int AMASK>
__device__ __forceinline__ void store_frag(float* __restrict__ Dst,
                                           const float* __restrict__ bias,
                                           bool relu, int m0, int n0,
                                           int g, int tg, const float c[8][4]) {
    int rot = tg << 3;
    int pm0 = (m0 + g + rot) & AMASK;
    int pm1 = (m0 + g + 8 + rot) & AMASK;
    #pragma unroll
    for (int j = 0; j < 8; ++j) {
        int na = n0 + 16 * tg + j;
        int nb = na + 8;
        float ba_ = bias[na], bb_ = bias[nb];
        float v0 = c[j][0] + ba_, v1 = c[j][1] + bb_;
        float v2 = c[j][2] + ba_, v3 = c[j][3] + bb_;
        if (relu) {
            v0 = fmaxf(v0, 0.f); v1 = fmaxf(v1, 0.f);
            v2 = fmaxf(v2, 0.f); v3 = fmaxf(v3, 0.f);
        }
        Dst[(size_t)na * APAD + pm0] = v0;
        Dst[(size_t)nb * APAD + pm0] = v1;
        Dst[(size_t)na * APAD + pm1] = v2;
        Dst[(size_t)nb * APAD + pm1] = v3;
    }
}

// LN: XT = LN(XT + UT)*gamma + beta (both k-major rotated). 2 units per thread.
template<int APAD, int AMASK, int NT>
__device__ __forceinline__ void ln_t(float* __restrict__ XT,
                                     const float* __restrict__ UT,
                                     const float* __restrict__ gamma,
                                     const float* __restrict__ beta) {
    int tid = threadIdx.x;
    #pragma unroll
    for (int u = 0; u < 2; ++u) {
        int idx  = tid + u * NT;
        int node = idx >> 3;
        int h    = idx & 7;
        float v[16];
        float sum = 0.f;
        #pragma unroll
        for (int i = 0; i < 16; ++i) {
            int e  = h + 8 * i;
            int pn = (node + (((i >> 1) & 3) << 3)) & AMASK;   // KROT(e)
            v[i] = XT[e * APAD + pn] + UT[e * APAD + pn];
            sum += v[i];
        }
        sum += __shfl_xor_sync(0xffffffffu, sum, 1);
        sum += __shfl_xor_sync(0xffffffffu, sum, 2);
        sum += __shfl_xor_sync(0xffffffffu, sum, 4);
        float m = sum * (1.f / 128.f);
        float sq = 0.f;
        #pragma unroll
        for (int i = 0; i < 16; ++i) { float d = v[i] - m; sq = fmaf(d, d, sq); }
        sq += __shfl_xor_sync(0xffffffffu, sq, 1);
        sq += __shfl_xor_sync(0xffffffffu, sq, 2);
        sq += __shfl_xor_sync(0xffffffffu, sq, 4);
        float inv = rsqrtf(sq * (1.f / 128.f) + EPS_LN);
        #pragma unroll
        for (int i = 0; i < 16; ++i) {
            int e  = h + 8 * i;
            int pn = (node + (((i >> 1) & 3) << 3)) & AMASK;
            XT[e * APAD + pn] = (v[i] - m) * inv * gamma[e] + beta[e];
        }
    }
}

// ---------------- one transformer layer (main, 128-node tile) ----------------
__device__ void run_layer(SmemMain* s, int base,
                          const float* wq, const float* wo, const float* bo,
                          const float* wa, const float* ba,
                          const float* wb, const float* bb,
                          const float* ga, const float* bea,
                          const float* gb, const float* beb,
                          const float* __restrict__ Kp,
                          const float* __restrict__ Vp) {
    int tid  = threadIdx.x;
    int lane = tid & 31, warp = tid >> 5;
    int g  = lane >> 2, tg = lane & 3;
    int m0 = (warp & 7) * 16;      // 0..112
    int n0 = (warp >> 3) * 64;     // 0 or 64
    float* Tq = s->S;              // row-major 128 x TQS
    float c[8][4];

    // ---- 1. Q = X @ wq -> Tq ----
    zc(c);
    stage_full<MTHREADS>(wq, 0, 0, DIM, s->W);
    gemm_mma<MPAD, 127, 16>(s->XT, s->W, m0, n0, g, tg, c);
    #pragma unroll
    for (int j = 0; j < 8; ++j) {
        int na = n0 + 16 * tg + j;
        int nb = na + 8;
        Tq[(size_t)(m0 + g) * TQS + na]     = c[j][0];
        Tq[(size_t)(m0 + g) * TQS + nb]     = c[j][1];
        Tq[(size_t)(m0 + g + 8) * TQS + na] = c[j][2];
        Tq[(size_t)(m0 + g + 8) * TQS + nb] = c[j][3];
    }
    __syncthreads();   // Tq visible; W readers done

    // prefetch wo (full) while attention gathers run
    issue_full<MTHREADS>(wo, 0, 0, DIM, s->W);
    cp_commit();

    // ---- 2. attention: 2 (node,head) units per thread; node = idx>>3, h = idx&7
    // warp = 4 consecutive nodes x 8 heads -> gather LDGs touch 16 lines, not 32
    float4 o2[2][4];
    #pragma unroll
    for (int u = 0; u < 2; ++u) {
        #pragma unroll
        for (int t = 0; t < 4; ++t) o2[u][t] = make_float4(0.f, 0.f, 0.f, 0.f);
        int idx  = tid + u * MTHREADS;
        int node = idx >> 3;
        int h    = idx & 7;
        int gg   = base + node;
        if (gg < N_NODES) {
            const float* qs = Tq + node * TQS + h * 16;
            float q[16];
            #pragma unroll
            for (int t = 0; t < 4; ++t) {
                float4 q4 = *(const float4*)(qs + t * 4);
                q[4*t] = q4.x; q[4*t+1] = q4.y; q[4*t+2] = q4.z; q[4*t+3] = q4.w;
            }
            float dots[KNBR]; bool msk[KNBR];
            #pragma unroll
            for (int j = 0; j < KNBR; ++j) {
                int mflag = s->nmask[node * KNBR + j];
                msk[j] = (mflag != 0);
                if (mflag) { dots[j] = -1e30f; continue; }
                int nb = s->nidx[node * KNBR + j];
                const float4* kp = (const float4*)(Kp + (size_t)nb * DIM + h * 16);
                float d = 0.f;
                #pragma unroll
                for (int t = 0; t < 4; ++t) {
                    float4 k4 = kp[t];
                    d = fmaf(q[4*t+0], k4.x, d);
                    d = fmaf(q[4*t+1], k4.y, d);
                    d = fmaf(q[4*t+2], k4.z, d);
                    d = fmaf(q[4*t+3], k4.w, d);
                }
                dots[j] = d * 0.25f;
            }
            float mmax = -1e30f;
            #pragma unroll
            for (int j = 0; j < KNBR; ++j) mmax = fmaxf(mmax, dots[j]);
            float e[KNBR]; float ssum = 0.f;
            #pragma unroll
            for (int j = 0; j < KNBR; ++j) {
                e[j] = msk[j] ? 0.f : __expf(dots[j] - mmax);
                ssum += e[j];
            }
            float inv = 1.f / ssum;
            #pragma unroll
            for (int j = 0; j < KNBR; ++j) {
                if (!msk[j]) {
                    int nb = s->nidx[node * KNBR + j];
                    const float4* vp = (const float4*)(Vp + (size_t)nb * DIM + h * 16);
                    float a = e[j] * inv;
                    #pragma unroll
                    for (int t = 0; t < 4; ++t) {
                        float4 v4 = vp[t];
                        o2[u][t].x = fmaf(a, v4.x, o2[u][t].x);
                        o2[u][t].y = fmaf(a, v4.y, o2[u][t].y);
                        o2[u][t].z = fmaf(a, v4.z, o2[u][t].z);
                        o2[u][t].w = fmaf(a, v4.w, o2[u][t].w);
                    }
                }
            }
        }
    }
    __syncthreads();   // everyone finished reading Tq
    #pragma unroll
    for (int u = 0; u < 2; ++u) {
        int idx  = tid + u * MTHREADS;
        int node = idx >> 3;
        int h    = idx & 7;
        int pn   = (node + ((h & 3) << 3)) & 127;   // KROT(cc), cc>>4 == h
        #pragma unroll
        for (int t = 0; t < 4; ++t) {
            int cc = h * 16 + t * 4;
            s->S[(cc + 0) * MPAD + pn] = o2[u][t].x;
            s->S[(cc + 1) * MPAD + pn] = o2[u][t].y;
            s->S[(cc + 2) * MPAD + pn] = o2[u][t].z;
            s->S[(cc + 3) * MPAD + pn] = o2[u][t].w;
        }
    }
    cp_waitall();
    __syncthreads();   // AT + wo ready

    // ---- 3. U = attn @ wo + bo ----
    zc(c);
    gemm_mma<MPAD, 127, 16>(s->S, s->W, m0, n0, g, tg, c);
    __syncthreads();                 // all done reading AT (S) and W
    store_frag<MPAD, 127>(s->S, bo, false, m0, n0, g, tg, c);   // U over AT
    issue_full<MTHREADS>(wa, 0, 0, 256, s->W);   // prefetch wa half0 during LN
    cp_commit();
    __syncthreads();                 // U visible

    // ---- 4. X = LN(X + U) ----
    ln_t<MPAD, 127, MTHREADS>(s->XT, s->S, ga, bea);
    cp_waitall();
    __syncthreads();                 // LN'd XT + wa0 ready; S free

    // ---- 5/6. FFN ----
    float cF[8][4]; zc(cF);
    // h = 0
    zc(c);
    gemm_mma<MPAD, 127, 16>(s->XT, s->W, m0, n0, g, tg, c);       // H0
    store_frag<MPAD, 127>(s->S, ba, true, m0, n0, g, tg, c);      // H0 -> S
    stage_full<MTHREADS>(wb, 0, 0, DIM, s->W);                    // sync: H0 visible, W free
    gemm_mma<MPAD, 127, 16>(s->S, s->W, m0, n0, g, tg, cF);
    // h = 1
    stage_full<MTHREADS>(wa, 0, 128, 256, s->W);                  // sync: S readers done
    zc(c);
    gemm_mma<MPAD, 127, 16>(s->XT, s->W, m0, n0, g, tg, c);       // H1
    store_frag<MPAD, 127>(s->S, ba + 128, true, m0, n0, g, tg, c);
    stage_full<MTHREADS>(wb, 128, 0, DIM, s->W);                  // sync: H1 visible
    gemm_mma<MPAD, 127, 16>(s->S, s->W, m0, n0, g, tg, cF);
    __syncthreads();                // all done reading H (S)
    store_frag<MPAD, 127>(s->S, bb, false, m0, n0, g, tg, cF);    // F
    __syncthreads();

    // ---- 7. X = LN(X + F) ----
    ln_t<MPAD, 127, MTHREADS>(s->XT, s->S, gb, beb);
    __syncthreads();
}

// ---------------- kernel 1: Kp/Vp projections + row sums (round-14 winner) ----
extern "C" __global__ void __launch_bounds__(PTHREADS, 3)
pre_kernel(const float* __restrict__ feat,
           const float* __restrict__ wk1, const float* __restrict__ wv1,
           const float* __restrict__ wk2, const float* __restrict__ wv2) {
    extern __shared__ char smem_raw[];
    SmemPre* s = (SmemPre*)smem_raw;
    int tid  = threadIdx.x;
    int base = blockIdx.x * PBLOCK;

    #pragma unroll
    for (int i = tid; i < PBLOCK * 32; i += PTHREADS) {
        int node = i >> 5;
        int k4   = (i & 31) << 2;
        int gg   = base + node;
        float4 v = make_float4(0.f, 0.f, 0.f, 0.f);
        if (gg < N_NODES) v = *(const float4*)(feat + (size_t)gg * DIM + k4);
        int pn = (node + KROT(k4)) & 63;
        s->XT[(k4 + 0) * PPAD + pn] = v.x;
        s->XT[(k4 + 1) * PPAD + pn] = v.y;
        s->XT[(k4 + 2) * PPAD + pn] = v.z;
        s->XT[(k4 + 3) * PPAD + pn] = v.w;
    }
    __syncthreads();

    {   // row sums (2 units per thread)
        #pragma unroll
        for (int u = 0; u < 2; ++u) {
            int idx  = tid + u * PTHREADS;
            int node = idx >> 3;
            int h    = idx & 7;
            float ssum = 0.f;
            #pragma unroll
            for (int i = 0; i < 16; ++i) {
                int e  = h + 8 * i;
                int pn = (node + (((i >> 1) & 3) << 3)) & 63;
                ssum += s->XT[e * PPAD + pn];
            }
            ssum += __shfl_xor_sync(0xffffffffu, ssum, 1);
            ssum += __shfl_xor_sync(0xffffffffu, ssum, 2);
            ssum += __shfl_xor_sync(0xffffffffu, ssum, 4);
            int gg = base + node;
            if (h == 0 && gg < N_NODES) g_rowsum[gg] = ssum;
        }
    }

    int lane = tid & 31, warp = tid >> 5;
    int g  = lane >> 2, tg = lane & 3;
    int m0 = (warp & 3) * 16;
    int n0 = (warp >> 2) * 64;
    const float* ws_in[4] = {wk1, wv1, wk2, wv2};
    float* outs[4] = {g_Kp1, g_Vp1, g_Kp2, g_Vp2};
    float c[8][4];
    #pragma unroll
    for (int w = 0; w < 4; ++w) {
        zc(c);
        stage_chunk<PTHREADS>(ws_in[w], 0, 0, DIM, s->W);
        gemm_mma<PPAD, 63, 8>(s->XT, s->W, m0, n0, g, tg, c);
        stage_chunk<PTHREADS>(ws_in[w], 64, 0, DIM, s->W);
        gemm_mma<PPAD, 63, 8>(s->XT + 64 * PPAD, s->W, m0, n0, g, tg, c);
        float* op = outs[w];
        int gm0 = base + m0 + g;
        int gm1 = gm0 + 8;
        int nb0 = n0 + 16 * tg;
        if (gm0 < N_NODES) {
            *(float4*)(op + (size_t)gm0 * DIM + nb0)      = make_float4(c[0][0], c[1][0], c[2][0], c[3][0]);
            *(float4*)(op + (size_t)gm0 * DIM + nb0 + 4)  = make_float4(c[4][0], c[5][0], c[6][0], c[7][0]);
            *(float4*)(op + (size_t)gm0 * DIM + nb0 + 8)  = make_float4(c[0][1], c[1][1], c[2][1], c[3][1]);
            *(float4*)(op + (size_t)gm0 * DIM + nb0 + 12) = make_float4(c[4][1], c[5][1], c[6][1], c[7][1]);
        }
        if (gm1 < N_NODES) {
            *(float4*)(op + (size_t)gm1 * DIM + nb0)      = make_float4(c[0][2], c[1][2], c[2][2], c[3][2]);
            *(float4*)(op + (size_t)gm1 * DIM + nb0 + 4)  = make_float4(c[4][2], c[5][2], c[6][2], c[7][2]);
            *(float4*)(op + (size_t)gm1 * DIM + nb0 + 8)  = make_float4(c[0][3], c[1][3], c[2][3], c[3][3]);
            *(float4*)(op + (size_t)gm1 * DIM + nb0 + 12) = make_float4(c[4][3], c[5][3], c[6][3], c[7][3]);
        }
    }
}

// ---------------- kernel 2: fused 2-layer transformer + head (128-node tiles) --
extern "C" __global__ void __launch_bounds__(MTHREADS, 1)
main_kernel(const float* __restrict__ feat,
            const int* __restrict__ nbr_idx,
            const int* __restrict__ nbr_valid,
            const float* wq1, const float* wo1, const float* bo1,
            const float* w1a, const float* b1a, const float* w1b, const float* b1b,
            const float* g1a, const float* be1a, const float* g1b, const float* be1b,
            const float* wq2, const float* wo2, const float* bo2,
            const float* w2a, const float* b2a, const float* w2b, const float* b2b,
            const float* g2a, const float* be2a, const float* g2b, const float* be2b,
            const float* w4, const float* b4,
            float* __restrict__ out) {
    extern __shared__ char smem_raw[];
    SmemMain* s = (SmemMain*)smem_raw;
    int tid  = threadIdx.x;
    int base = blockIdx.x * MBLOCK;

    #pragma unroll
    for (int i = tid; i < MBLOCK * 32; i += MTHREADS) {
        int node = i >> 5;
        int k4   = (i & 31) << 2;
        int gg   = base + node;
        float4 v = make_float4(0.f, 0.f, 0.f, 0.f);
        if (gg < N_NODES) v = *(const float4*)(feat + (size_t)gg * DIM + k4);
        int pn = (node + KROT(k4)) & 127;
        s->XT[(k4 + 0) * MPAD + pn] = v.x;
        s->XT[(k4 + 1) * MPAD + pn] = v.y;
        s->XT[(k4 + 2) * MPAD + pn] = v.z;
        s->XT[(k4 + 3) * MPAD + pn] = v.w;
    }
    for (int i = tid; i < MBLOCK * KNBR; i += MTHREADS) {
        int node = i / KNBR;
        int j    = i - node * KNBR;
        int gg   = base + node;
        int idx = 0, mflag = 1;
        if (gg < N_NODES) {
            idx = nbr_idx[(size_t)gg * KNBR + j];
            int valid = nbr_valid[(size_t)gg * KNBR + j];   // nonzero = true
            mflag = (valid == 0) || (g_rowsum[idx] == 0.f);
        }
        s->nidx[i]  = idx;
        s->nmask[i] = mflag;
    }
    __syncthreads();

    run_layer(s, base, wq1, wo1, bo1, w1a, b1a, w1b, b1b,
              g1a, be1a, g1b, be1b, g_Kp1, g_Vp1);
    run_layer(s, base, wq2, wo2, bo2, w2a, b2a, w2b, b2b,
              g2a, be2a, g2b, be2b, g_Kp2, g_Vp2);

    // ---- head: out = tanh(X @ w4 + b4), w4: 128x64 (row stride 64, unswizzled) --
    __syncthreads();
    {
        #pragma unroll
        for (int i = tid; i < 2048; i += MTHREADS) {   // 2048 float4
            int r  = i >> 4;
            int c4 = (i & 15) << 2;
            cp16(sptr(s->W + r * 64 + c4), w4 + r * 64 + c4);
        }
        cp_commit();
        cp_waitall();
    }
    __syncthreads();
    #pragma unroll
    for (int u = 0; u < 2; ++u) {
        int idx  = tid + u * MTHREADS;
        int node = idx >> 3;
        int c0   = (idx & 7) * 8;
        float acc8[8];
        #pragma unroll
        for (int c = 0; c < 8; ++c) acc8[c] = 0.f;
        #pragma unroll 4
        for (int kk = 0; kk < DIM; ++kk) {
            int pn = (node + KROT(kk)) & 127;
            float a = s->XT[kk * MPAD + pn];
            float4 w0 = *(const float4*)(s->W + kk * 64 + c0);
            float4 w1 = *(const float4*)(s->W + kk * 64 + c0 + 4);
            acc8[0] = fmaf(a, w0.x, acc8[0]);
            acc8[1] = fmaf(a, w0.y, acc8[1]);
            acc8[2] = fmaf(a, w0.z, acc8[2]);
            acc8[3] = fmaf(a, w0.w, acc8[3]);
            acc8[4] = fmaf(a, w1.x, acc8[4]);
            acc8[5] = fmaf(a, w1.y, acc8[5]);
            acc8[6] = fmaf(a, w1.z, acc8[6]);
            acc8[7] = fmaf(a, w1.w, acc8[7]);
        }
        int gg = base + node;
        if (gg < N_NODES) {
            #pragma unroll
            for (int c = 0; c < 8; ++c)
                out[(size_t)gg * 64 + c0 + c] = tanhf(acc8[c] + b4[c0 + c]);
        }
    }
}

// ---------------- host launch ----------------
extern "C" void kernel_launch(void* const* d_in, const int* in_sizes, int n_in,
                              void* d_out, int out_size) {
    const float* feat  = (const float*)d_in[0];
    const int* nbr_idx = (const int*)d_in[1];
    const int* nbr_val = (const int*)d_in[2];
    const float* wq1 = (const float*)d_in[3];
    const float* wk1 = (const float*)d_in[4];
    const float* wv1 = (const float*)d_in[5];
    const float* wo1 = (const float*)d_in[6];
    const float* bo1 = (const float*)d_in[7];
    const float* w1a = (const float*)d_in[8];
    const float* b1a = (const float*)d_in[9];
    const float* w1b = (const float*)d_in[10];
    const float* b1b = (const float*)d_in[11];
    const float* g1a = (const float*)d_in[12];
    const float* be1a = (const float*)d_in[13];
    const float* g1b = (const float*)d_in[14];
    const float* be1b = (const float*)d_in[15];
    const float* wq2 = (const float*)d_in[16];
    const float* wk2 = (const float*)d_in[17];
    const float* wv2 = (const float*)d_in[18];
    const float* wo2 = (const float*)d_in[19];
    const float* bo2 = (const float*)d_in[20];
    const float* w2a = (const float*)d_in[21];
    const float* b2a = (const float*)d_in[22];
    const float* w2b = (const float*)d_in[23];
    const float* b2b = (const float*)d_in[24];
    const float* g2a = (const float*)d_in[25];
    const float* be2a = (const float*)d_in[26];
    const float* g2b = (const float*)d_in[27];
    const float* be2b = (const float*)d_in[28];
    const float* w4 = (const float*)d_in[29];
    const float* b4 = (const float*)d_in[30];
    float* out = (float*)d_out;

    cudaFuncSetAttribute(pre_kernel,  cudaFuncAttributeMaxDynamicSharedMemorySize,
                         (int)sizeof(SmemPre));
    cudaFuncSetAttribute(main_kernel, cudaFuncAttributeMaxDynamicSharedMemorySize,
                         (int)sizeof(SmemMain));

    pre_kernel<<<PTILES, PTHREADS, sizeof(SmemPre)>>>(feat, wk1, wv1, wk2, wv2);
    main_kernel<<<MTILES, MTHREADS, sizeof(SmemMain)>>>(
        feat, nbr_idx, nbr_val,
        wq1, wo1, bo1, w1a, b1a, w1b, b1b, g1a, be1a, g1b, be1b,
        wq2, wo2, bo2, w2a, b2a, w2b, b2b, g2a, be2a, g2b, be2b,
        w4, b4, out);
}